// round 4
// baseline (speedup 1.0000x reference)
#include <cuda_runtime.h>
#include <cstdint>

// ---------------------------------------------------------------------------
// QuantSoftmax (I-BERT IntSoftmax) on GB300.
// x: (1,12,2048,2048) f32. out: same shape f32 = out_int / 256.
//
// Pipeline:
//   k0: reset global absmax
//   k1: global absmax of x                      (one pass, 201 MB read)
//   k2: <<<1,1>>> derive all scalar constants (f32 ops mirroring jnp; f64 for
//       the fixedpoint_mul constants, folded into a single multiplier K)
//   k3: per-row kernel (1 CTA / 2048-elem row): quant round-trip, row max,
//       shift-exp, float-float requantize, row sum, fixed-point normalize.
// ---------------------------------------------------------------------------

struct Scalars {
    float sf;      // symmetric 16-bit scale
    float rsf;     // RN(1/sf)
    float x0i;     // floor(X0/sf)  (negative)
    float rx0i;    // RN(1/x0i)
    float xclamp;  // 30 * x0i
    float bint;    // floor(COEF1/sf)
    float cint;    // floor(COEF2/sf^2)
    float Khi;     // hi part of f64 requant multiplier K
    float Klo;     // lo part
};

__device__ Scalars      g_sc;
__device__ unsigned int g_amax_bits;

__global__ void init_kernel() { g_amax_bits = 0u; }

// ---------------------------------------------------------------------------
// k1: global absmax (non-negative floats compare correctly as uint bits)
// ---------------------------------------------------------------------------
__global__ __launch_bounds__(256) void absmax_kernel(const float4* __restrict__ xv, int n4) {
    float m = 0.0f;
    for (int i = blockIdx.x * 256 + threadIdx.x; i < n4; i += gridDim.x * 256) {
        float4 v = xv[i];
        m = fmaxf(m, fmaxf(fmaxf(fabsf(v.x), fabsf(v.y)),
                           fmaxf(fabsf(v.z), fabsf(v.w))));
    }
#pragma unroll
    for (int o = 16; o > 0; o >>= 1)
        m = fmaxf(m, __shfl_xor_sync(0xffffffffu, m, o));
    __shared__ float sm[8];
    if ((threadIdx.x & 31) == 0) sm[threadIdx.x >> 5] = m;
    __syncthreads();
    if (threadIdx.x == 0) {
        float b = sm[0];
#pragma unroll
        for (int i = 1; i < 8; i++) b = fmaxf(b, sm[i]);
        atomicMax(&g_amax_bits, __float_as_uint(b));
    }
}

// ---------------------------------------------------------------------------
// k2: scalar constants (mirrors jnp f32 op sequence exactly; f64 for
// fixedpoint_mul constants). exp_int.max() is analytically floor(c_int*2^30):
// every row has xi==0 at its max after the row-max subtraction, and the
// polynomial is monotone on (x0_int, 0], so that element is the global max;
// exp_int.min() >= 0 so sym_scale only sees the max.
// ---------------------------------------------------------------------------
__global__ void scalars_kernel() {
    float amax = __uint_as_float(g_amax_bits);
    float s1   = fmaxf(amax, 1e-8f);
    float sf   = __fdiv_rn(s1, 32767.0f);

    float x0i  = floorf(__fdiv_rn((float)(-0.6931), sf));
    float bint = floorf(__fdiv_rn((float)(0.96963238 / 0.35815147), sf));
    float sf2  = __fmul_rn(sf, sf);
    float cint = floorf(__fdiv_rn((float)(1.0 / 0.35815147), sf2));

    float exp_sf  = __fmul_rn(__fmul_rn((float)0.35815147, sf2), 0x1p-30f);
    float exp_max = floorf(__fmul_rn(cint, 0x1p30f));
    float act_sf  = __fdiv_rn(fmaxf(exp_max, 1e-8f), 32767.0f);

    // fixedpoint_mul constants (reference does this in f64):
    //   new_scale = f32(exp_sf/act_sf); e = floor(log2(|ns|))+1 == frexp exp;
    //   m_int = rint(mant * 2^31);  per-element: rint(z_int * m_int * 2^(e-31))
    //   with z_int = exp_int/exp_sf (inner rint is identity at ~1e29+).
    // Fold into one multiplier K.
    double ns = (double)__fdiv_rn(exp_sf, act_sf);
    int e;
    double mant  = frexp(ns, &e);
    double m_int = rint(mant * 2147483648.0);
    double K     = ldexp(m_int, e - 31) / (double)exp_sf;

    Scalars sc;
    sc.sf     = sf;
    sc.rsf    = __fdiv_rn(1.0f, sf);
    sc.x0i    = x0i;
    sc.rx0i   = __fdiv_rn(1.0f, x0i);
    sc.xclamp = __fmul_rn(30.0f, x0i);
    sc.bint   = bint;
    sc.cint   = cint;
    sc.Khi    = (float)K;
    sc.Klo    = (float)(K - (double)sc.Khi);
    g_sc = sc;
}

// Markstein correctly-rounded division a/b given rb = RN(1/b).
// Bit-identical to div.rn.f32 for finite normal operands; 3 FMA-pipe ops.
__device__ __forceinline__ float fdiv_exact(float a, float b, float rb) {
    float q0 = __fmul_rn(a, rb);
    float r  = __fmaf_rn(-b, q0, a);
    return __fmaf_rn(r, rb, q0);
}

// ---------------------------------------------------------------------------
// k3: one CTA per 2048-element row; 256 threads x 8 elements.
// ---------------------------------------------------------------------------
__global__ __launch_bounds__(256) void qsoftmax_kernel(const float* __restrict__ x,
                                                       float* __restrict__ out) {
    __shared__ float sred[8];
    __shared__ float sb;

    const Scalars sc = g_sc;
    const int row = blockIdx.x;
    const int t   = threadIdx.x;
    const float4* xv = reinterpret_cast<const float4*>(x) + (size_t)row * 512;
    float4*       ov = reinterpret_cast<float4*>(out) + (size_t)row * 512;

    float4 a0 = xv[t];
    float4 a1 = xv[t + 256];
    float v[8] = {a0.x, a0.y, a0.z, a0.w, a1.x, a1.y, a1.z, a1.w};

    // quant round-trip: xi = (clip(rint(x/sf)) * sf) / sf   (all f32, exact)
    float xi[8];
    float m = -3.4e38f;
#pragma unroll
    for (int i = 0; i < 8; i++) {
        float tt = fdiv_exact(v[i], sc.sf, sc.rsf);
        float q  = rintf(tt);
        q        = fminf(fmaxf(q, -32768.0f), 32767.0f);
        float qx = __fmul_rn(q, sc.sf);
        xi[i]    = fdiv_exact(qx, sc.sf, sc.rsf);
        m        = fmaxf(m, xi[i]);
    }

    // row max
#pragma unroll
    for (int o = 16; o > 0; o >>= 1)
        m = fmaxf(m, __shfl_xor_sync(0xffffffffu, m, o));
    if ((t & 31) == 0) sred[t >> 5] = m;
    __syncthreads();
    if (t == 0) {
        float b = sred[0];
#pragma unroll
        for (int i = 1; i < 8; i++) b = fmaxf(b, sred[i]);
        sb = b;
    }
    __syncthreads();
    const float rowmax = sb;

    float e16[8];
    float s = 0.0f;
#pragma unroll
    for (int i = 0; i < 8; i++) {
        float z = __fsub_rn(xi[i], rowmax);
        z = fmaxf(z, sc.xclamp);

        // int_exp: q = floor(z/x0), r = z - x0*q, poly, * 2^(30-q)
        float qf = floorf(fdiv_exact(z, sc.x0i, sc.rx0i));
        float r  = __fsub_rn(z, __fmul_rn(sc.x0i, qf));
        float pol = __fadd_rn(__fmul_rn(r, __fadd_rn(r, sc.bint)), sc.cint);
        int   qi  = (int)qf;                      // q in [0,30]
        float pw  = __int_as_float((157 - qi) << 23);  // exact 2^(30-q)
        float u   = __fmul_rn(pol, pw);
        float ei  = fmaxf(floorf(u), 0.0f);

        // fixedpoint requantize: rint(ei * K) at ~f64 accuracy via float-float
        float p    = __fmul_rn(ei, sc.Khi);
        float perr = __fmaf_rn(ei, sc.Khi, -p);        // exact product residual
        float lo   = __fmaf_rn(ei, sc.Klo, perr);
        float n0   = rintf(p);                         // half-even on hi part
        float d    = __fadd_rn(__fsub_rn(p, n0), lo);  // p-n0 exact (Sterbenz)
        n0 = (d >  0.5f) ? n0 + 1.0f : n0;
        n0 = (d < -0.5f) ? n0 - 1.0f : n0;
        n0 = fminf(fmaxf(n0, -32768.0f), 32767.0f);
        e16[i] = n0;
        s = __fadd_rn(s, n0);
    }

    // row sum
#pragma unroll
    for (int o = 16; o > 0; o >>= 1)
        s = __fadd_rn(s, __shfl_xor_sync(0xffffffffu, s, o));
    if ((t & 31) == 0) sred[t >> 5] = s;
    __syncthreads();
    if (t == 0) {
        float b = sred[0];
#pragma unroll
        for (int i = 1; i < 8; i++) b = __fadd_rn(b, sred[i]);
        sb = b;
    }
    __syncthreads();
    const float rs = sb;

    const float factor = floorf(__fdiv_rn(4294967296.0f, rs));

    float o8[8];
#pragma unroll
    for (int i = 0; i < 8; i++) {
        float oi = floorf(__fmul_rn(__fmul_rn(e16[i], factor), 0x1p-24f));
        o8[i] = __fmul_rn(oi, 0x1p-8f);
    }
    ov[t]       = make_float4(o8[0], o8[1], o8[2], o8[3]);
    ov[t + 256] = make_float4(o8[4], o8[5], o8[6], o8[7]);
}

// ---------------------------------------------------------------------------
extern "C" void kernel_launch(void* const* d_in, const int* in_sizes, int n_in,
                              void* d_out, int out_size) {
    const float* x = (const float*)d_in[0];
    float* out = (float*)d_out;
    const int n    = in_sizes[0];
    const int n4   = n / 4;
    const int rows = n / 2048;

    init_kernel<<<1, 1>>>();
    absmax_kernel<<<2048, 256>>>((const float4*)x, n4);
    scalars_kernel<<<1, 1>>>();
    qsoftmax_kernel<<<rows, 256>>>(x, out);
}

// round 5
// speedup vs baseline: 1.1661x; 1.1661x over previous
#include <cuda_runtime.h>
#include <cstdint>

// ---------------------------------------------------------------------------
// QuantSoftmax (I-BERT IntSoftmax) on GB300 — round 5.
// Packed f32x2 math (FFMA2), exact-RN-preserving; reverse row order for L2
// reuse of the absmax pass; __ldcs/__stcs to control L2 pollution.
// ---------------------------------------------------------------------------

struct Scalars {
    float sf;      // symmetric 16-bit scale
    float rsf;     // RN(1/sf)
    float x0i;     // floor(X0/sf)  (negative integer-valued)
    float rx0i;    // RN(1/x0i)
    float xclamp;  // 30 * x0i
    float bint;    // floor(COEF1/sf)
    float cint;    // floor(COEF2/sf^2)
    float Khi;     // hi part of f64 requant multiplier K
    float Klo;     // lo part
};

__device__ Scalars      g_sc;
__device__ unsigned int g_amax_bits;

__global__ void init_kernel() { g_amax_bits = 0u; }

// ---------------------------------------------------------------------------
// packed f32x2 helpers (sm_100+ PTX; ptxas never emits these from C++)
// ---------------------------------------------------------------------------
__device__ __forceinline__ uint64_t pk2(float lo, float hi) {
    uint64_t r; asm("mov.b64 %0, {%1, %2};" : "=l"(r) : "f"(lo), "f"(hi)); return r;
}
__device__ __forceinline__ void upk2(uint64_t v, float& lo, float& hi) {
    asm("mov.b64 {%0, %1}, %2;" : "=f"(lo), "=f"(hi) : "l"(v));
}
__device__ __forceinline__ uint64_t f2mul(uint64_t a, uint64_t b) {
    uint64_t d; asm("mul.rn.f32x2 %0, %1, %2;" : "=l"(d) : "l"(a), "l"(b)); return d;
}
__device__ __forceinline__ uint64_t f2add(uint64_t a, uint64_t b) {
    uint64_t d; asm("add.rn.f32x2 %0, %1, %2;" : "=l"(d) : "l"(a), "l"(b)); return d;
}
__device__ __forceinline__ uint64_t f2fma(uint64_t a, uint64_t b, uint64_t c) {
    uint64_t d; asm("fma.rn.f32x2 %0, %1, %2, %3;" : "=l"(d) : "l"(a), "l"(b), "l"(c)); return d;
}

// ---------------------------------------------------------------------------
// k1: global absmax. Streams the whole tensor; its tail stays in L2 for k3.
// ---------------------------------------------------------------------------
__global__ __launch_bounds__(256) void absmax_kernel(const float4* __restrict__ xv, int n4) {
    float m = 0.0f;
#pragma unroll 8
    for (int i = blockIdx.x * 256 + threadIdx.x; i < n4; i += gridDim.x * 256) {
        float4 v = xv[i];
        m = fmaxf(m, fmaxf(fmaxf(fabsf(v.x), fabsf(v.y)),
                           fmaxf(fabsf(v.z), fabsf(v.w))));
    }
#pragma unroll
    for (int o = 16; o > 0; o >>= 1)
        m = fmaxf(m, __shfl_xor_sync(0xffffffffu, m, o));
    __shared__ float sm[8];
    if ((threadIdx.x & 31) == 0) sm[threadIdx.x >> 5] = m;
    __syncthreads();
    if (threadIdx.x == 0) {
        float b = sm[0];
#pragma unroll
        for (int i = 1; i < 8; i++) b = fmaxf(b, sm[i]);
        atomicMax(&g_amax_bits, __float_as_uint(b));
    }
}

// ---------------------------------------------------------------------------
// k2: scalar constants (f32 ops mirror jnp; f64 for fixedpoint_mul, folded
// into one multiplier K). exp_int.max() is analytically floor(c_int*2^30).
// ---------------------------------------------------------------------------
__global__ void scalars_kernel() {
    float amax = __uint_as_float(g_amax_bits);
    float s1   = fmaxf(amax, 1e-8f);
    float sf   = __fdiv_rn(s1, 32767.0f);

    float x0i  = floorf(__fdiv_rn((float)(-0.6931), sf));
    float bint = floorf(__fdiv_rn((float)(0.96963238 / 0.35815147), sf));
    float sf2  = __fmul_rn(sf, sf);
    float cint = floorf(__fdiv_rn((float)(1.0 / 0.35815147), sf2));

    float exp_sf  = __fmul_rn(__fmul_rn((float)0.35815147, sf2), 0x1p-30f);
    float exp_max = floorf(__fmul_rn(cint, 0x1p30f));
    float act_sf  = __fdiv_rn(fmaxf(exp_max, 1e-8f), 32767.0f);

    double ns = (double)__fdiv_rn(exp_sf, act_sf);
    int e;
    double mant  = frexp(ns, &e);
    double m_int = rint(mant * 2147483648.0);
    double K     = ldexp(m_int, e - 31) / (double)exp_sf;

    Scalars sc;
    sc.sf     = sf;
    sc.rsf    = __fdiv_rn(1.0f, sf);
    sc.x0i    = x0i;
    sc.rx0i   = __fdiv_rn(1.0f, x0i);
    sc.xclamp = __fmul_rn(30.0f, x0i);
    sc.bint   = bint;
    sc.cint   = cint;
    sc.Khi    = (float)K;
    sc.Klo    = (float)(K - (double)sc.Khi);
    g_sc = sc;
}

// ---------------------------------------------------------------------------
// k3: one CTA per 2048-element row; 256 threads x 8 elems (4 packed pairs).
// Rows processed in REVERSE so the tail of x (still in L2 from absmax) hits.
// ---------------------------------------------------------------------------
__global__ __launch_bounds__(256) void qsoftmax_kernel(const float* __restrict__ x,
                                                       float* __restrict__ out,
                                                       int rows) {
    __shared__ float sred[8];
    __shared__ float sbv;

    const Scalars sc = g_sc;
    const int row = rows - 1 - blockIdx.x;
    const int t   = threadIdx.x;
    const float4* xv = reinterpret_cast<const float4*>(x) + (size_t)row * 512;
    float4*       ov = reinterpret_cast<float4*>(out) + (size_t)row * 512;

    float4 a0 = __ldcs(xv + t);
    float4 a1 = __ldcs(xv + t + 256);

    const uint64_t RSF  = pk2(sc.rsf, sc.rsf);
    const uint64_t NSF  = pk2(-sc.sf, -sc.sf);
    const uint64_t SF2  = pk2(sc.sf, sc.sf);
    const uint64_t MAG  = pk2(12582912.0f, 12582912.0f);   // 1.5*2^23
    const uint64_t NMAG = pk2(-12582912.0f, -12582912.0f);

    uint64_t v2[4] = { pk2(a0.x, a0.y), pk2(a0.z, a0.w),
                       pk2(a1.x, a1.y), pk2(a1.z, a1.w) };
    uint64_t xi2[4];
    float m = -3.4e38f;

    // quant round-trip: xi = RN(RN(rint(x/sf)*sf)/sf); divisions via Markstein
    // (exact RN-div given rsf); rint via magic (half-even, |tt| <= 32767).
#pragma unroll
    for (int i = 0; i < 4; i++) {
        uint64_t q0 = f2mul(v2[i], RSF);
        uint64_t rr = f2fma(q0, NSF, v2[i]);
        uint64_t tt = f2fma(rr, RSF, q0);
        uint64_t q  = f2add(f2add(tt, MAG), NMAG);     // rint; clamps never bind
        uint64_t qx = f2mul(q, SF2);
        uint64_t p0 = f2mul(qx, RSF);
        uint64_t p1 = f2fma(p0, NSF, qx);
        xi2[i]      = f2fma(p1, RSF, p0);
        float xa, xb; upk2(xi2[i], xa, xb);
        m = fmaxf(m, fmaxf(xa, xb));
    }

    // row max reduction
#pragma unroll
    for (int o = 16; o > 0; o >>= 1)
        m = fmaxf(m, __shfl_xor_sync(0xffffffffu, m, o));
    if ((t & 31) == 0) sred[t >> 5] = m;
    __syncthreads();
    if (t == 0) {
        float b = sred[0];
#pragma unroll
        for (int i = 1; i < 8; i++) b = fmaxf(b, sred[i]);
        sbv = b;
    }
    __syncthreads();
    const float rowmax = sbv;

    const uint64_t NRM = pk2(-rowmax, -rowmax);
    const uint64_t RX0 = pk2(sc.rx0i, sc.rx0i);
    const uint64_t NX0 = pk2(-sc.x0i, -sc.x0i);
    const uint64_t B2  = pk2(sc.bint, sc.bint);
    const uint64_t C2  = pk2(sc.cint, sc.cint);
    const uint64_t KH  = pk2(sc.Khi, sc.Khi);
    const uint64_t NKH = pk2(-sc.Khi, -sc.Khi);
    const uint64_t NKL = pk2(-sc.Klo, -sc.Klo);
    const uint64_t N1  = pk2(-1.0f, -1.0f);

    uint64_t e2[4];
    uint64_t s2 = pk2(0.0f, 0.0f);
#pragma unroll
    for (int i = 0; i < 4; i++) {
        uint64_t z = f2add(xi2[i], NRM);
        float za, zb; upk2(z, za, zb);
        za = fmaxf(za, sc.xclamp);
        zb = fmaxf(zb, sc.xclamp);
        uint64_t zz = pk2(za, zb);

        // q = floor(z/x0i)  (exact RN-div then floor)
        uint64_t q0 = f2mul(zz, RX0);
        uint64_t rr = f2fma(q0, NX0, zz);
        uint64_t tq = f2fma(rr, RX0, q0);
        float qa, qb; upk2(tq, qa, qb);
        qa = floorf(qa);
        qb = floorf(qb);
        // 2^(30-q) exactly via exponent-bit construction
        float pwa = __int_as_float((157 - __float2int_rz(qa)) << 23);
        float pwb = __int_as_float((157 - __float2int_rz(qb)) << 23);
        uint64_t qf = pk2(qa, qb);

        // r = z - x0i*q (product exact -> fma == mul+sub of reference)
        uint64_t r2  = f2fma(qf, NX0, zz);
        uint64_t pol = f2fma(r2, f2add(r2, B2), C2);
        uint64_t u   = f2mul(pol, pk2(pwa, pwb));
        float ua, ub; upk2(u, ua, ub);
        uint64_t ei = pk2(floorf(ua), floorf(ub));   // pol > 0 on (x0i,0] -> no max(.,0)

        // requant: rint(ei*K) at f64 accuracy via float-float
        uint64_t p     = f2mul(ei, KH);
        uint64_t nperr = f2fma(ei, NKH, p);          // -(ei*Khi - p)
        uint64_t nlo   = f2fma(ei, NKL, nperr);      // -(ei*Klo + perr)
        uint64_t n0    = f2add(f2add(p, MAG), NMAG); // rint(p), half-even
        uint64_t pn    = f2fma(n0, N1, p);           // p - n0 (exact)
        uint64_t d     = f2fma(nlo, N1, pn);         // (p-n0) + lo
        uint64_t adj   = f2add(f2add(d, MAG), NMAG); // rint(d): +-1 iff |d|>0.5
        n0 = f2add(n0, adj);                         // clamps provably never bind
        e2[i] = n0;
        s2 = f2add(s2, n0);
    }

    // row sum (all partials are exact integers < 2^24 -> order-exact)
    float sa, sb2; upk2(s2, sa, sb2);
    float s = __fadd_rn(sa, sb2);
#pragma unroll
    for (int o = 16; o > 0; o >>= 1)
        s = __fadd_rn(s, __shfl_xor_sync(0xffffffffu, s, o));
    if ((t & 31) == 0) sred[t >> 5] = s;
    __syncthreads();
    if (t == 0) {
        float b = sred[0];
#pragma unroll
        for (int i = 1; i < 8; i++) b = __fadd_rn(b, sred[i]);
        sbv = b;
    }
    __syncthreads();
    const float rs = sbv;

    const float factor = floorf(__fdiv_rn(4294967296.0f, rs));
    const float ffs    = __fmul_rn(factor, 0x1p-24f);   // exact p2 scale fold
    const uint64_t FF  = pk2(ffs, ffs);
    const uint64_t P8  = pk2(0x1p-8f, 0x1p-8f);

    float o8[8];
#pragma unroll
    for (int i = 0; i < 4; i++) {
        uint64_t w = f2mul(e2[i], FF);
        float wa, wb; upk2(w, wa, wb);
        uint64_t fo = f2mul(pk2(floorf(wa), floorf(wb)), P8);
        upk2(fo, o8[2 * i], o8[2 * i + 1]);
    }
    __stcs(ov + t,       make_float4(o8[0], o8[1], o8[2], o8[3]));
    __stcs(ov + t + 256, make_float4(o8[4], o8[5], o8[6], o8[7]));
}

// ---------------------------------------------------------------------------
extern "C" void kernel_launch(void* const* d_in, const int* in_sizes, int n_in,
                              void* d_out, int out_size) {
    const float* x = (const float*)d_in[0];
    float* out = (float*)d_out;
    const int n    = in_sizes[0];
    const int n4   = n / 4;
    const int rows = n / 2048;

    init_kernel<<<1, 1>>>();
    absmax_kernel<<<2048, 256>>>((const float4*)x, n4);
    scalars_kernel<<<1, 1>>>();
    qsoftmax_kernel<<<rows, 256>>>(x, out, rows);
}